// round 10
// baseline (speedup 1.0000x reference)
#include <cuda_runtime.h>

#define NQ      8
#define KCODES  1024
#define DIM     64
#define TOKENS  65536
#define TILE    128         // codes per smem tile
#define C       4           // codes per lane (lane + 32*cc)
#define CTA     128         // threads per CTA (4 warps)
#define WARPS   4
#define TPW     16          // tokens per warp
#define PAD     16          // residual row: 64B, 16B-aligned

typedef unsigned long long u64;
typedef unsigned int u32;

__device__ float g_csq[NQ * KCODES];

__device__ __forceinline__ void ffma2(u64& acc, u64 a, u64 b) {
    asm("fma.rn.f32x2 %0, %1, %2, %0;" : "+l"(acc) : "l"(a), "l"(b));
}
__device__ __forceinline__ u64 add2(u64 a, u64 b) {
    u64 r;
    asm("add.rn.f32x2 %0, %1, %2;" : "=l"(r) : "l"(a), "l"(b));
    return r;
}
__device__ __forceinline__ u64 dup2(float v) {
    u64 r;
    asm("mov.b64 %0, {%1, %1};" : "=l"(r) : "f"(v));
    return r;
}
__device__ __forceinline__ u64 pack2(float lo, float hi) {
    u64 r;
    asm("mov.b64 %0, {%1, %2};" : "=l"(r) : "f"(lo), "f"(hi));
    return r;
}
__device__ __forceinline__ void unpack2(float& lo, float& hi, u64 v) {
    asm("mov.b64 {%0, %1}, %2;" : "=f"(lo), "=f"(hi) : "l"(v));
}
// monotone float->u32, key = score:code (min key == first-min argmin)
__device__ __forceinline__ u64 make_key(float s, u32 idx) {
    u32 b = __float_as_uint(s);
    u32 u = b ^ (u32)(((int)b >> 31) | 0x80000000);
    return ((u64)u << 32) | idx;
}
__device__ __forceinline__ u32 smem_u32(const void* p) {
    u32 a;
    asm("{ .reg .u64 t; cvta.to.shared.u64 t, %1; cvt.u32.u64 %0, t; }"
        : "=r"(a) : "l"(p));
    return a;
}
__device__ __forceinline__ void cp_async16(u32 dst, const void* src) {
    asm volatile("cp.async.cg.shared.global [%0], [%1], 16;"
                 :: "r"(dst), "l"(src) : "memory");
}

__global__ void csq_kernel(const float* __restrict__ cb) {
    int r = blockIdx.x * blockDim.x + threadIdx.x;
    const float4* row = reinterpret_cast<const float4*>(cb + (size_t)r * DIM);
    float s = 0.f;
#pragma unroll
    for (int i = 0; i < DIM / 4; i++) {
        float4 v = row[i];
        s = __fadd_rn(s, __fmul_rn(v.x, v.x));
        s = __fadd_rn(s, __fmul_rn(v.y, v.y));
        s = __fadd_rn(s, __fmul_rn(v.z, v.z));
        s = __fadd_rn(s, __fmul_rn(v.w, v.w));
    }
    g_csq[r] = s;
}

__global__ void __launch_bounds__(CTA, 4)
rvq_kernel(const float* __restrict__ x,
           const float* __restrict__ cb,
           float* __restrict__ out) {
    extern __shared__ float sm[];
    float4* smT4 = reinterpret_cast<float4*>(sm);          // [16][TILE] float4, 32KB
    float*  smr_ = sm + (DIM / 4) * TILE * 4;              // [WARPS][DIM][PAD], 16KB

    const int tid  = threadIdx.x;
    const int wid  = tid >> 5;
    const int lane = tid & 31;
    const int tokenBase = blockIdx.x * (WARPS * TPW) + wid * TPW;

    float* myr = smr_ + wid * DIM * PAD;   // [DIM][PAD] token = column
    const u32 smT4_b = smem_u32(smT4);

    // init: lane t<16 owns token t. residual = x, rsq fused (sequential d-asc)
    float rs = 0.f;
    if (lane < TPW) {
        const float4* xr = reinterpret_cast<const float4*>(
            x + (size_t)(tokenBase + lane) * DIM);
#pragma unroll
        for (int i = 0; i < DIM / 4; i++) {
            float4 v = xr[i];
            myr[(4 * i + 0) * PAD + lane] = v.x;
            myr[(4 * i + 1) * PAD + lane] = v.y;
            myr[(4 * i + 2) * PAD + lane] = v.z;
            myr[(4 * i + 3) * PAD + lane] = v.w;
            rs = __fadd_rn(rs, __fmul_rn(v.x, v.x));
            rs = __fadd_rn(rs, __fmul_rn(v.y, v.y));
            rs = __fadd_rn(rs, __fmul_rn(v.z, v.z));
            rs = __fadd_rn(rs, __fmul_rn(v.w, v.w));
        }
    }
    __syncwarp();

#pragma unroll 1
    for (int q = 0; q < NQ; q++) {
        const float* cbq = cb + (size_t)q * KCODES * DIM;

        // broadcast rsq to packed per-token-pair form
        u64 rsq2[TPW / 2];
#pragma unroll
        for (int p = 0; p < TPW / 2; p++) {
            float lo = __shfl_sync(0xffffffffu, rs, 2 * p);
            float hi = __shfl_sync(0xffffffffu, rs, 2 * p + 1);
            rsq2[p] = pack2(lo, hi);
        }

        float bests[TPW];
        u32   win[TPW / 4];
#pragma unroll
        for (int t = 0; t < TPW; t++) bests[t] = __int_as_float(0x7f800000);
#pragma unroll
        for (int w = 0; w < TPW / 4; w++) win[w] = 0u;

#pragma unroll 1
        for (int c = 0; c < KCODES / TILE; c++) {
            __syncthreads();
            {   // cp.async tile load: thread owns code tid
                const float4* src = reinterpret_cast<const float4*>(
                    cbq + (size_t)(c * TILE + tid) * DIM);
#pragma unroll
                for (int i = 0; i < DIM / 4; i++)
                    cp_async16(smT4_b + (u32)((i * TILE + tid) * 16), src + i);
                asm volatile("cp.async.commit_group;" ::: "memory");
                asm volatile("cp.async.wait_group 0;" ::: "memory");
            }
            __syncthreads();

            float cs[C];
#pragma unroll
            for (int cc = 0; cc < C; cc++)
                cs[cc] = g_csq[q * KCODES + c * TILE + lane + 32 * cc];

            u64 acc[C][TPW / 2];
#pragma unroll
            for (int cc = 0; cc < C; cc++)
#pragma unroll
                for (int p = 0; p < TPW / 2; p++) acc[cc][p] = 0ull;

#pragma unroll 2
            for (int dc = 0; dc < DIM / 4; dc++) {
                float4 cv[C];                        // per-lane distinct LDS.128
#pragma unroll
                for (int cc = 0; cc < C; cc++)
                    cv[cc] = smT4[dc * TILE + lane + 32 * cc];
#pragma unroll
                for (int j = 0; j < 4; j++) {
                    const ulonglong2* rrow = reinterpret_cast<const ulonglong2*>(
                        myr + (dc * 4 + j) * PAD);
                    ulonglong2 r0 = rrow[0];         // tokens 0-3 (broadcast)
                    ulonglong2 r1 = rrow[1];
                    ulonglong2 r2 = rrow[2];
                    ulonglong2 r3 = rrow[3];
#pragma unroll
                    for (int cc = 0; cc < C; cc++) {
                        float csv = (j == 0) ? cv[cc].x : (j == 1) ? cv[cc].y
                                  : (j == 2) ? cv[cc].z : cv[cc].w;
                        u64 a = dup2(csv);
                        ffma2(acc[cc][0], a, r0.x);
                        ffma2(acc[cc][1], a, r0.y);
                        ffma2(acc[cc][2], a, r1.x);
                        ffma2(acc[cc][3], a, r1.y);
                        ffma2(acc[cc][4], a, r2.x);
                        ffma2(acc[cc][5], a, r2.y);
                        ffma2(acc[cc][6], a, r3.x);
                        ffma2(acc[cc][7], a, r3.y);
                    }
                }
            }

            // scores: s = (rsq - 2*dot) + csq ; strict-< first-min (c,cc asc)
            const u64 NEG2 = 0xC0000000C0000000ull;
#pragma unroll
            for (int cc = 0; cc < C; cc++) {
                u64 csd  = dup2(cs[cc]);
                u32 wid8 = (u32)((c << 2) | cc);     // 5-bit winner id
#pragma unroll
                for (int p = 0; p < TPW / 2; p++) {
                    u64 t0 = rsq2[p];
                    ffma2(t0, acc[cc][p], NEG2);
                    u64 s0 = add2(t0, csd);
                    float a, b;
                    unpack2(a, b, s0);
                    {
                        const int t = 2 * p;
                        bool lt = a < bests[t];
                        bests[t] = lt ? a : bests[t];
                        u32 ins = __byte_perm(win[t >> 2], wid8,
                                              (0x3210 & ~(0xFu << (4 * (t & 3))))
                                              | (0x4u << (4 * (t & 3))));
                        win[t >> 2] = lt ? ins : win[t >> 2];
                    }
                    {
                        const int t = 2 * p + 1;
                        bool lt = b < bests[t];
                        bests[t] = lt ? b : bests[t];
                        u32 ins = __byte_perm(win[t >> 2], wid8,
                                              (0x3210 & ~(0xFu << (4 * (t & 3))))
                                              | (0x4u << (4 * (t & 3))));
                        win[t >> 2] = lt ? ins : win[t >> 2];
                    }
                }
            }
        }

        // rebuild exact keys, cross-lane first-min merge
        u64 key[TPW];
#pragma unroll
        for (int t = 0; t < TPW; t++) {
            u32 w   = (win[t >> 2] >> (8 * (t & 3))) & 0xFFu;
            u32 idx = (w >> 2) * TILE + 32 * (w & 3) + (u32)lane;
            key[t] = make_key(bests[t], idx);
        }
#pragma unroll
        for (int off = 16; off >= 1; off >>= 1) {
#pragma unroll
            for (int t = 0; t < TPW; t++) {
                u64 o = __shfl_xor_sync(0xffffffffu, key[t], off);
                if (o < key[t]) key[t] = o;
            }
        }

        // select my token's winner (keys identical across lanes)
        u32 bk_mine = 0;
#pragma unroll
        for (int t = 0; t < TPW; t++)
            if (lane == t) bk_mine = (u32)(key[t] & 0xFFFFull);

        // conflict-free update: lane t<16 owns token t; fused next-stage rsq
        rs = 0.f;
        if (lane < TPW) {
            const float4* crow = reinterpret_cast<const float4*>(
                cbq + (size_t)bk_mine * DIM);
#pragma unroll
            for (int i = 0; i < DIM / 4; i++) {
                float4 v = crow[i];
                float r0 = __fsub_rn(myr[(4 * i + 0) * PAD + lane], v.x);
                float r1 = __fsub_rn(myr[(4 * i + 1) * PAD + lane], v.y);
                float r2 = __fsub_rn(myr[(4 * i + 2) * PAD + lane], v.z);
                float r3 = __fsub_rn(myr[(4 * i + 3) * PAD + lane], v.w);
                myr[(4 * i + 0) * PAD + lane] = r0;
                myr[(4 * i + 1) * PAD + lane] = r1;
                myr[(4 * i + 2) * PAD + lane] = r2;
                myr[(4 * i + 3) * PAD + lane] = r3;
                rs = __fadd_rn(rs, __fmul_rn(r0, r0));
                rs = __fadd_rn(rs, __fmul_rn(r1, r1));
                rs = __fadd_rn(rs, __fmul_rn(r2, r2));
                rs = __fadd_rn(rs, __fmul_rn(r3, r3));
            }
        }
        __syncwarp();
    }

    // out = x - residual_final (once; conflicts here are negligible)
#pragma unroll 1
    for (int t = 0; t < TPW; t++) {
        const float* xr  = x   + (size_t)(tokenBase + t) * DIM;
        float*       orw = out + (size_t)(tokenBase + t) * DIM;
        orw[lane]      = __fsub_rn(xr[lane],      myr[lane * PAD + t]);
        orw[lane + 32] = __fsub_rn(xr[lane + 32], myr[(lane + 32) * PAD + t]);
    }
}

extern "C" void kernel_launch(void* const* d_in, const int* in_sizes, int n_in,
                              void* d_out, int out_size) {
    const float* x;
    const float* cb;
    if (in_sizes[0] == NQ * KCODES * DIM) {
        cb = (const float*)d_in[0];
        x  = (const float*)d_in[1];
    } else {
        x  = (const float*)d_in[0];
        cb = (const float*)d_in[1];
    }
    float* out = (float*)d_out;

    const int smem_bytes = ((DIM / 4) * TILE * 4 + WARPS * DIM * PAD)
                           * (int)sizeof(float);
    cudaFuncSetAttribute(rvq_kernel,
                         cudaFuncAttributeMaxDynamicSharedMemorySize, smem_bytes);

    csq_kernel<<<(NQ * KCODES) / 128, 128>>>(cb);
    rvq_kernel<<<TOKENS / (WARPS * TPW), CTA, smem_bytes>>>(x, cb, out);
}

// round 11
// speedup vs baseline: 1.0739x; 1.0739x over previous
#include <cuda_runtime.h>

#define NQ      8
#define KCODES  1024
#define DIM     64
#define TOKENS  65536
#define TILE    128         // codes per smem tile
#define C       4           // codes per lane (lane + 32*cc)
#define CTA     128         // threads per CTA (4 warps)
#define WARPS   4
#define TPW     16          // tokens per warp
#define PAD     16          // residual row: 64B, 16B-aligned

typedef unsigned long long u64;
typedef unsigned int u32;

__device__ float g_csq[NQ * KCODES];

__device__ __forceinline__ void ffma2(u64& acc, u64 a, u64 b) {
    asm("fma.rn.f32x2 %0, %1, %2, %0;" : "+l"(acc) : "l"(a), "l"(b));
}
__device__ __forceinline__ u64 add2(u64 a, u64 b) {
    u64 r;
    asm("add.rn.f32x2 %0, %1, %2;" : "=l"(r) : "l"(a), "l"(b));
    return r;
}
__device__ __forceinline__ u64 dup2(float v) {
    u64 r;
    asm("mov.b64 %0, {%1, %1};" : "=l"(r) : "f"(v));
    return r;
}
__device__ __forceinline__ void unpack2(float& lo, float& hi, u64 v) {
    asm("mov.b64 {%0, %1}, %2;" : "=f"(lo), "=f"(hi) : "l"(v));
}
// monotone float->u32, key = score:code (min key == first-min argmin)
__device__ __forceinline__ u64 make_key(float s, u32 idx) {
    u32 b = __float_as_uint(s);
    u32 u = b ^ (u32)(((int)b >> 31) | 0x80000000);
    return ((u64)u << 32) | idx;
}
__device__ __forceinline__ u32 smem_u32(const void* p) {
    u32 a;
    asm("{ .reg .u64 t; cvta.to.shared.u64 t, %1; cvt.u32.u64 %0, t; }"
        : "=r"(a) : "l"(p));
    return a;
}
__device__ __forceinline__ void cp_async16(u32 dst, const void* src) {
    asm volatile("cp.async.cg.shared.global [%0], [%1], 16;"
                 :: "r"(dst), "l"(src) : "memory");
}

__global__ void csq_kernel(const float* __restrict__ cb) {
    int r = blockIdx.x * blockDim.x + threadIdx.x;
    const float4* row = reinterpret_cast<const float4*>(cb + (size_t)r * DIM);
    float s = 0.f;
#pragma unroll
    for (int i = 0; i < DIM / 4; i++) {
        float4 v = row[i];
        s = __fadd_rn(s, __fmul_rn(v.x, v.x));
        s = __fadd_rn(s, __fmul_rn(v.y, v.y));
        s = __fadd_rn(s, __fmul_rn(v.z, v.z));
        s = __fadd_rn(s, __fmul_rn(v.w, v.w));
    }
    g_csq[r] = s;
}

__global__ void __launch_bounds__(CTA, 3)
rvq_kernel(const float* __restrict__ x,
           const float* __restrict__ cb,
           float* __restrict__ out) {
    extern __shared__ float sm[];
    float4* smT4   = reinterpret_cast<float4*>(sm);        // [16][TILE] float4, 32KB
    float*  smr_   = sm + (DIM / 4) * TILE * 4;            // [WARPS][DIM][PAD], 16KB
    float*  smrsq_ = smr_ + WARPS * DIM * PAD;             // [WARPS][16]

    const int tid  = threadIdx.x;
    const int wid  = tid >> 5;
    const int lane = tid & 31;
    const int tokenBase = blockIdx.x * (WARPS * TPW) + wid * TPW;

    float* myr   = smr_ + wid * DIM * PAD;   // [DIM][PAD] token = column
    float* myrsq = smrsq_ + wid * TPW;
    const u32 smT4_b = smem_u32(smT4);

    // init: lane t<16 owns token t. residual = x, rsq fused (sequential d-asc)
    if (lane < TPW) {
        const float4* xr = reinterpret_cast<const float4*>(
            x + (size_t)(tokenBase + lane) * DIM);
        float rs = 0.f;
#pragma unroll
        for (int i = 0; i < DIM / 4; i++) {
            float4 v = xr[i];
            myr[(4 * i + 0) * PAD + lane] = v.x;
            myr[(4 * i + 1) * PAD + lane] = v.y;
            myr[(4 * i + 2) * PAD + lane] = v.z;
            myr[(4 * i + 3) * PAD + lane] = v.w;
            rs = __fadd_rn(rs, __fmul_rn(v.x, v.x));
            rs = __fadd_rn(rs, __fmul_rn(v.y, v.y));
            rs = __fadd_rn(rs, __fmul_rn(v.z, v.z));
            rs = __fadd_rn(rs, __fmul_rn(v.w, v.w));
        }
        myrsq[lane] = rs;
    }
    __syncwarp();

#pragma unroll 1
    for (int q = 0; q < NQ; q++) {
        const float* cbq = cb + (size_t)q * KCODES * DIM;

        float bests[TPW];
        u32   win[TPW / 4];
#pragma unroll
        for (int t = 0; t < TPW; t++) bests[t] = __int_as_float(0x7f800000);
#pragma unroll
        for (int w = 0; w < TPW / 4; w++) win[w] = 0u;

#pragma unroll 1
        for (int c = 0; c < KCODES / TILE; c++) {
            __syncthreads();
            {   // cp.async tile load: thread owns code tid
                const float4* src = reinterpret_cast<const float4*>(
                    cbq + (size_t)(c * TILE + tid) * DIM);
#pragma unroll
                for (int i = 0; i < DIM / 4; i++)
                    cp_async16(smT4_b + (u32)((i * TILE + tid) * 16), src + i);
                asm volatile("cp.async.commit_group;" ::: "memory");
                asm volatile("cp.async.wait_group 0;" ::: "memory");
            }
            __syncthreads();

            float cs[C];
#pragma unroll
            for (int cc = 0; cc < C; cc++)
                cs[cc] = g_csq[q * KCODES + c * TILE + lane + 32 * cc];

            u64 acc[C][TPW / 2];
#pragma unroll
            for (int cc = 0; cc < C; cc++)
#pragma unroll
                for (int p = 0; p < TPW / 2; p++) acc[cc][p] = 0ull;

            // ---- software-pipelined dot loop: rp loaded 1 j-step ahead ----
            const ulonglong2* rbase = reinterpret_cast<const ulonglong2*>(myr);
            // PAD floats = 16 floats = 4 ulonglong2 per row
            ulonglong2 a0 = rbase[0], a1 = rbase[1], a2 = rbase[2], a3 = rbase[3];

#pragma unroll 4
            for (int dc = 0; dc < DIM / 4; dc++) {
                float4 cv[C];                        // per-lane distinct LDS.128
#pragma unroll
                for (int cc = 0; cc < C; cc++)
                    cv[cc] = smT4[dc * TILE + lane + 32 * cc];
#pragma unroll
                for (int j = 0; j < 4; j++) {
                    // prefetch next row (d+1); last iter reloads row 0 (harmless)
                    int nrow = (dc * 4 + j + 1) & (DIM - 1);
                    const ulonglong2* rn = rbase + nrow * (PAD / 4);
                    ulonglong2 b0 = rn[0], b1 = rn[1], b2 = rn[2], b3 = rn[3];
#pragma unroll
                    for (int cc = 0; cc < C; cc++) {
                        float csv = (j == 0) ? cv[cc].x : (j == 1) ? cv[cc].y
                                  : (j == 2) ? cv[cc].z : cv[cc].w;
                        u64 a = dup2(csv);
                        ffma2(acc[cc][0], a, a0.x);
                        ffma2(acc[cc][1], a, a0.y);
                        ffma2(acc[cc][2], a, a1.x);
                        ffma2(acc[cc][3], a, a1.y);
                        ffma2(acc[cc][4], a, a2.x);
                        ffma2(acc[cc][5], a, a2.y);
                        ffma2(acc[cc][6], a, a3.x);
                        ffma2(acc[cc][7], a, a3.y);
                    }
                    a0 = b0; a1 = b1; a2 = b2; a3 = b3;
                }
            }

            // rsq pairs from smem (broadcast), scores, running first-min
            const u64 NEG2 = 0xC0000000C0000000ull;
            const u64* rsq2 = reinterpret_cast<const u64*>(myrsq);
#pragma unroll
            for (int cc = 0; cc < C; cc++) {
                u64 csd  = dup2(cs[cc]);
                u32 wid8 = (u32)((c << 2) | cc);     // 5-bit winner id
#pragma unroll
                for (int p = 0; p < TPW / 2; p++) {
                    u64 t0 = rsq2[p];                // broadcast LDS.64
                    ffma2(t0, acc[cc][p], NEG2);
                    u64 s0 = add2(t0, csd);
                    float a, b;
                    unpack2(a, b, s0);
                    {
                        const int t = 2 * p;
                        bool lt = a < bests[t];
                        bests[t] = lt ? a : bests[t];
                        u32 ins = __byte_perm(win[t >> 2], wid8,
                                              (0x3210 & ~(0xFu << (4 * (t & 3))))
                                              | (0x4u << (4 * (t & 3))));
                        win[t >> 2] = lt ? ins : win[t >> 2];
                    }
                    {
                        const int t = 2 * p + 1;
                        bool lt = b < bests[t];
                        bests[t] = lt ? b : bests[t];
                        u32 ins = __byte_perm(win[t >> 2], wid8,
                                              (0x3210 & ~(0xFu << (4 * (t & 3))))
                                              | (0x4u << (4 * (t & 3))));
                        win[t >> 2] = lt ? ins : win[t >> 2];
                    }
                }
            }
        }

        // rebuild exact keys, cross-lane first-min merge
        u64 key[TPW];
#pragma unroll
        for (int t = 0; t < TPW; t++) {
            u32 w   = (win[t >> 2] >> (8 * (t & 3))) & 0xFFu;
            u32 idx = (w >> 2) * TILE + 32 * (w & 3) + (u32)lane;
            key[t] = make_key(bests[t], idx);
        }
#pragma unroll
        for (int off = 16; off >= 1; off >>= 1) {
#pragma unroll
            for (int t = 0; t < TPW; t++) {
                u64 o = __shfl_xor_sync(0xffffffffu, key[t], off);
                if (o < key[t]) key[t] = o;
            }
        }

        // select my token's winner (keys identical across lanes)
        u32 bk_mine = 0;
#pragma unroll
        for (int t = 0; t < TPW; t++)
            if (lane == t) bk_mine = (u32)(key[t] & 0xFFFFull);

        // conflict-free update: lane t<16 owns token t; fused next-stage rsq
        if (lane < TPW) {
            const float4* crow = reinterpret_cast<const float4*>(
                cbq + (size_t)bk_mine * DIM);
            float rs = 0.f;
#pragma unroll
            for (int i = 0; i < DIM / 4; i++) {
                float4 v = crow[i];
                float r0 = __fsub_rn(myr[(4 * i + 0) * PAD + lane], v.x);
                float r1 = __fsub_rn(myr[(4 * i + 1) * PAD + lane], v.y);
                float r2 = __fsub_rn(myr[(4 * i + 2) * PAD + lane], v.z);
                float r3 = __fsub_rn(myr[(4 * i + 3) * PAD + lane], v.w);
                myr[(4 * i + 0) * PAD + lane] = r0;
                myr[(4 * i + 1) * PAD + lane] = r1;
                myr[(4 * i + 2) * PAD + lane] = r2;
                myr[(4 * i + 3) * PAD + lane] = r3;
                rs = __fadd_rn(rs, __fmul_rn(r0, r0));
                rs = __fadd_rn(rs, __fmul_rn(r1, r1));
                rs = __fadd_rn(rs, __fmul_rn(r2, r2));
                rs = __fadd_rn(rs, __fmul_rn(r3, r3));
            }
            myrsq[lane] = rs;
        }
        __syncwarp();
    }

    // out = x - residual_final
#pragma unroll 1
    for (int t = 0; t < TPW; t++) {
        const float* xr  = x   + (size_t)(tokenBase + t) * DIM;
        float*       orw = out + (size_t)(tokenBase + t) * DIM;
        orw[lane]      = __fsub_rn(xr[lane],      myr[lane * PAD + t]);
        orw[lane + 32] = __fsub_rn(xr[lane + 32], myr[(lane + 32) * PAD + t]);
    }
}

extern "C" void kernel_launch(void* const* d_in, const int* in_sizes, int n_in,
                              void* d_out, int out_size) {
    const float* x;
    const float* cb;
    if (in_sizes[0] == NQ * KCODES * DIM) {
        cb = (const float*)d_in[0];
        x  = (const float*)d_in[1];
    } else {
        x  = (const float*)d_in[0];
        cb = (const float*)d_in[1];
    }
    float* out = (float*)d_out;

    const int smem_bytes = ((DIM / 4) * TILE * 4 + WARPS * DIM * PAD
                            + WARPS * TPW) * (int)sizeof(float);
    cudaFuncSetAttribute(rvq_kernel,
                         cudaFuncAttributeMaxDynamicSharedMemorySize, smem_bytes);

    csq_kernel<<<(NQ * KCODES) / 128, 128>>>(cb);
    rvq_kernel<<<TOKENS / (WARPS * TPW), CTA, smem_bytes>>>(x, cb, out);
}